// round 16
// baseline (speedup 1.0000x reference)
#include <cuda_runtime.h>
#include <cuda_bf16.h>
#include <math.h>
#include <stdint.h>

static constexpr int B_ = 16, C_ = 16, P_ = 512, D_ = 256;

// Scratch (device globals; allocation in kernel_launch is forbidden)
__device__ __nv_bfloat16 g_context[(size_t)B_ * C_ * P_ * D_];  // [b,c][p][d]
__device__ __nv_bfloat16 g_qr[(size_t)B_ * C_ * P_ * D_];       // [b,c][p][d]
__device__ __nv_bfloat16 g_q[(size_t)B_ * C_ * P_ * D_];        // [b,c][p][e]
__device__ __nv_bfloat16 g_k[(size_t)B_ * C_ * P_ * D_];        // [b,c][p][e]
__device__ __nv_bfloat16 g_vT[(size_t)B_ * C_ * P_ * D_];       // [b,c][e][p]
__device__ __nv_bfloat16 g_wqT[(size_t)C_ * D_ * D_];           // [c][e][d]
__device__ __nv_bfloat16 g_wkT[(size_t)C_ * D_ * D_];
__device__ __nv_bfloat16 g_wvT[(size_t)C_ * D_ * D_];

// ---------------------------------------------------------------------------
// helpers
// ---------------------------------------------------------------------------
__device__ __forceinline__ uint32_t smem_u32(const void* p) {
    uint32_t a;
    asm("{ .reg .u64 t; cvta.to.shared.u64 t, %1; cvt.u32.u64 %0, t; }"
        : "=r"(a) : "l"(p));
    return a;
}
__device__ __forceinline__ void cpasync16(void* smem, const void* gmem) {
    unsigned s = (unsigned)__cvta_generic_to_shared(smem);
    asm volatile("cp.async.cg.shared.global [%0], [%1], 16;\n" :: "r"(s), "l"(gmem));
}
__device__ __forceinline__ void mma_bf16(float* c, const uint32_t* a, const uint32_t* b) {
    asm volatile(
        "mma.sync.aligned.m16n8k16.row.col.f32.bf16.bf16.f32 "
        "{%0,%1,%2,%3}, {%4,%5,%6,%7}, {%8,%9}, {%0,%1,%2,%3};"
        : "+f"(c[0]), "+f"(c[1]), "+f"(c[2]), "+f"(c[3])
        : "r"(a[0]), "r"(a[1]), "r"(a[2]), "r"(a[3]), "r"(b[0]), "r"(b[1]));
}
__device__ __forceinline__ void ldsm4(uint32_t& r0, uint32_t& r1,
                                      uint32_t& r2, uint32_t& r3, uint32_t addr) {
    asm volatile("ldmatrix.sync.aligned.m8n8.x4.shared.b16 {%0,%1,%2,%3}, [%4];"
                 : "=r"(r0), "=r"(r1), "=r"(r2), "=r"(r3) : "r"(addr));
}
__device__ __forceinline__ uint32_t packbf(float x, float y) {
    __nv_bfloat162 h = __floats2bfloat162_rn(x, y);
    return *(uint32_t*)&h;
}

// ---------------------------------------------------------------------------
// 0) transpose weights to bf16 [c][e][d]
// ---------------------------------------------------------------------------
__global__ void transpose_w_kernel(const float* __restrict__ wq,
                                   const float* __restrict__ wk,
                                   const float* __restrict__ wv)
{
    __shared__ float tile[32][33];
    int which = blockIdx.z / C_;
    int c     = blockIdx.z % C_;
    const float* src = (which == 0) ? wq : (which == 1) ? wk : wv;
    __nv_bfloat16* dst = (which == 0) ? g_wqT : (which == 1) ? g_wkT : g_wvT;
    src += (size_t)c * D_ * D_;
    dst += (size_t)c * D_ * D_;

    int x0 = blockIdx.x * 32;   // d
    int y0 = blockIdx.y * 32;   // e
    int tx = threadIdx.x, ty = threadIdx.y;
    #pragma unroll
    for (int j = 0; j < 4; j++)
        tile[ty + 8 * j][tx] = src[(size_t)(x0 + ty + 8 * j) * D_ + y0 + tx];
    __syncthreads();
    #pragma unroll
    for (int j = 0; j < 4; j++)
        dst[(size_t)(y0 + ty + 8 * j) * D_ + x0 + tx] =
            __float2bfloat16(tile[tx][ty + 8 * j]);
}

// ---------------------------------------------------------------------------
// 1) context = rowsum-over-C(aw*q) - aw*q, bf16 out; also bf16 query copy
// ---------------------------------------------------------------------------
__global__ void context_kernel(const float* __restrict__ query,
                               const float* __restrict__ aw)
{
    int idx = blockIdx.x * blockDim.x + threadIdx.x;   // over B*P*D/2 (pairs)
    if (idx >= B_ * P_ * D_ / 2) return;
    int b  = idx / (P_ * D_ / 2);
    int pd = (idx - b * (P_ * D_ / 2)) * 2;

    const float* qb  = query + (size_t)b * C_ * P_ * D_ + pd;
    const float* awp = aw + pd;

    float q0[C_], q1[C_], a0[C_], a1[C_];
    float s0 = 0.f, s1 = 0.f;
    #pragma unroll
    for (int c = 0; c < C_; c++) {
        float2 q = *(const float2*)(qb + (size_t)c * P_ * D_);
        float2 w = *(const float2*)(awp + (size_t)c * P_ * D_);
        q0[c] = q.x; q1[c] = q.y;
        a0[c] = w.x * q.x; a1[c] = w.y * q.y;
        s0 += a0[c]; s1 += a1[c];
    }
    __nv_bfloat16* ctx = g_context + (size_t)b * C_ * P_ * D_ + pd;
    __nv_bfloat16* qr  = g_qr + (size_t)b * C_ * P_ * D_ + pd;
    #pragma unroll
    for (int c = 0; c < C_; c++) {
        *(uint32_t*)(ctx + (size_t)c * P_ * D_) = packbf(s0 - a0[c], s1 - a1[c]);
        *(uint32_t*)(qr + (size_t)c * P_ * D_)  = packbf(q0[c], q1[c]);
    }
}

// ---------------------------------------------------------------------------
// 2) ALL THREE projections in one launch. grid = (8, 3*BC), 128 threads.
//    seg = by/BC: 0: q = relu(qr@wqT^T + bq)*scale   (512x256, MODE1)
//                 1: k = relu(ctx@wkT^T + bk)        (512x256, MODE1)
//                 2: vT = relu(wvT@ctx^T + rowbias)  (256x512, MODE2)
//    CTA 128x128, 4 warps, 64x64 warp tiles; BK=64, 2-stage cp.async.
// ---------------------------------------------------------------------------
__global__ __launch_bounds__(128, 2)
void proj_gemm(const __nv_bfloat16* __restrict__ qr0,
               const __nv_bfloat16* __restrict__ ctx0,
               const __nv_bfloat16* __restrict__ wqT0,
               const __nv_bfloat16* __restrict__ wkT0,
               const __nv_bfloat16* __restrict__ wvT0,
               const float* __restrict__ bq0,
               const float* __restrict__ bk0,
               const float* __restrict__ bv0,
               __nv_bfloat16* __restrict__ q0,
               __nv_bfloat16* __restrict__ k0,
               __nv_bfloat16* __restrict__ vT0,
               float qscale)
{
    constexpr int BK = 64;
    constexpr int SA = 72;
    constexpr int STG = 128 * SA;
    constexpr int BC = B_ * C_;
    const size_t PD = (size_t)P_ * D_;
    const size_t DD = (size_t)D_ * D_;

    extern __shared__ __nv_bfloat16 sh[];
    __nv_bfloat16* As = sh;
    __nv_bfloat16* Bs = sh + 2 * STG;

    const int tid  = threadIdx.x;
    const int lane = tid & 31;
    const int warp = tid >> 5;
    const int wm = warp >> 1;
    const int wn = warp & 1;

    const int seg = blockIdx.y / BC;
    const int z   = blockIdx.y % BC;
    const int bx  = blockIdx.x;
    const int c   = z % C_;

    // per-segment geometry (CTA-uniform)
    const __nv_bfloat16 *Ap, *Bp;
    const float* bias;
    __nv_bfloat16* Cp;
    int m_blk, n_blk, ldc;
    int mode;            // 1 = col-bias+relu(+scale), 2 = row-bias+relu
    float scale;
    if (seg == 0) {
        m_blk = (bx >> 1) * 128; n_blk = (bx & 1) * 128;
        Ap = qr0 + (size_t)z * PD + (size_t)m_blk * D_;
        Bp = wqT0 + (size_t)c * DD + (size_t)n_blk * D_;
        bias = bq0; Cp = q0 + (size_t)z * PD; ldc = D_;
        mode = 1; scale = qscale;
    } else if (seg == 1) {
        m_blk = (bx >> 1) * 128; n_blk = (bx & 1) * 128;
        Ap = ctx0 + (size_t)z * PD + (size_t)m_blk * D_;
        Bp = wkT0 + (size_t)c * DD + (size_t)n_blk * D_;
        bias = bk0; Cp = k0 + (size_t)z * PD; ldc = D_;
        mode = 1; scale = 1.0f;
    } else {
        m_blk = (bx >> 2) * 128; n_blk = (bx & 3) * 128;
        Ap = wvT0 + (size_t)c * DD + (size_t)m_blk * D_;
        Bp = ctx0 + (size_t)z * PD + (size_t)n_blk * D_;
        bias = bv0; Cp = vT0 + (size_t)z * PD; ldc = P_;
        mode = 2; scale = 1.0f;
    }

    float acc[4][8][4];
    #pragma unroll
    for (int i = 0; i < 4; i++)
        #pragma unroll
        for (int j = 0; j < 8; j++)
            #pragma unroll
            for (int r = 0; r < 4; r++) acc[i][j][r] = 0.f;

    auto load_tile = [&](int k0_, int buf) {
        __nv_bfloat16* Asb = As + buf * STG;
        __nv_bfloat16* Bsb = Bs + buf * STG;
        #pragma unroll
        for (int i = 0; i < 8; i++) {
            int idx = i * 128 + tid;
            int r = idx >> 3, cc = (idx & 7) * 8;
            cpasync16(Asb + r * SA + cc, Ap + (size_t)r * D_ + k0_ + cc);
            cpasync16(Bsb + r * SA + cc, Bp + (size_t)r * D_ + k0_ + cc);
        }
        asm volatile("cp.async.commit_group;\n");
    };

    constexpr int NT = D_ / BK;    // 4
    load_tile(0, 0);

    const int g  = lane >> 3;
    const int rw = lane & 7;
    const uint32_t smA = smem_u32(As);
    const uint32_t smB = smem_u32(Bs);
    const uint32_t aBase = smA + ((uint32_t)((wm * 64 + (g & 1) * 8 + rw) * SA
                                             + (g >> 1) * 8) << 1);
    const uint32_t bBase = smB + ((uint32_t)((wn * 64 + (g >> 1) * 8 + rw) * SA
                                             + (g & 1) * 8) << 1);

    #pragma unroll 1
    for (int t = 0; t < NT; t++) {
        if (t + 1 < NT) {
            load_tile((t + 1) * BK, (t + 1) & 1);
            asm volatile("cp.async.wait_group 1;\n");
        } else {
            asm volatile("cp.async.wait_group 0;\n");
        }
        __syncthreads();

        const uint32_t stOff = (uint32_t)((t & 1) * STG) << 1;
        const uint32_t sA = aBase + stOff;
        const uint32_t sB = bBase + stOff;

        #pragma unroll
        for (int ks = 0; ks < BK; ks += 16) {
            uint32_t afr[4][4];
            #pragma unroll
            for (int i = 0; i < 4; i++)
                ldsm4(afr[i][0], afr[i][1], afr[i][2], afr[i][3],
                      sA + (uint32_t)((i * 16 * SA + ks) << 1));
            uint32_t bfr[8][2];
            #pragma unroll
            for (int j2 = 0; j2 < 4; j2++)
                ldsm4(bfr[2 * j2][0], bfr[2 * j2][1],
                      bfr[2 * j2 + 1][0], bfr[2 * j2 + 1][1],
                      sB + (uint32_t)((j2 * 16 * SA + ks) << 1));
            #pragma unroll
            for (int i = 0; i < 4; i++)
                #pragma unroll
                for (int j = 0; j < 8; j++)
                    mma_bf16(acc[i][j], afr[i], bfr[j]);
        }
        __syncthreads();
    }

    // ----- epilogue -----
    #pragma unroll
    for (int j = 0; j < 8; j++) {
        int cidx = n_blk + wn * 64 + j * 8 + 2 * (lane & 3);
        float cb0 = 0.f, cb1 = 0.f;
        if (mode == 1) {
            const float* bp = bias + (size_t)c * D_ + cidx;
            cb0 = bp[0]; cb1 = bp[1];
        }
        #pragma unroll
        for (int i = 0; i < 4; i++) {
            int r0 = m_blk + wm * 64 + i * 16 + (lane >> 2);
            float v0 = acc[i][j][0], v1 = acc[i][j][1];
            float v2 = acc[i][j][2], v3 = acc[i][j][3];
            if (mode == 1) {
                v0 = fmaxf(v0 + cb0, 0.f) * scale;
                v1 = fmaxf(v1 + cb1, 0.f) * scale;
                v2 = fmaxf(v2 + cb0, 0.f) * scale;
                v3 = fmaxf(v3 + cb1, 0.f) * scale;
            } else {
                float rb0 = bias[(size_t)c * D_ + r0];
                float rb1 = bias[(size_t)c * D_ + r0 + 8];
                v0 = fmaxf(v0 + rb0, 0.f);
                v1 = fmaxf(v1 + rb0, 0.f);
                v2 = fmaxf(v2 + rb1, 0.f);
                v3 = fmaxf(v3 + rb1, 0.f);
            }
            *(uint32_t*)(Cp + (size_t)r0 * ldc + cidx)       = packbf(v0, v1);
            *(uint32_t*)(Cp + (size_t)(r0 + 8) * ldc + cidx) = packbf(v2, v3);
        }
    }
}

// ---------------------------------------------------------------------------
// 3) Fully fused attention: out[64x256] = softmax(q[64xD] @ k^T) @ vT^T.
// ---------------------------------------------------------------------------
static constexpr int FL_SA    = 72;
static constexpr int FL_BSTG  = 512 * FL_SA;
static constexpr int FL_ASTG  = 64 * FL_SA;
static constexpr int FL_A_OFF = 2 * FL_BSTG * 2;
static constexpr int FL_ST_OFF = FL_A_OFF + 2 * FL_ASTG * 2;
static constexpr int FL_SMEM  = FL_ST_OFF + 64 * 8 * 4;      // 167936 B
static constexpr int FL_AT_OFF = 0;
static constexpr int FL_SA2    = 520;
static constexpr int FL_V_OFF  = 66560;
static constexpr int FL_VSTG   = 256 * FL_SA;

__global__ __launch_bounds__(256, 1)
void fused_attn_kernel(const __nv_bfloat16* __restrict__ Q0,
                       const __nv_bfloat16* __restrict__ K0,
                       const __nv_bfloat16* __restrict__ V0,
                       float* __restrict__ O0)
{
    extern __shared__ char shraw[];
    __nv_bfloat16* Bs = (__nv_bfloat16*)(shraw);
    __nv_bfloat16* As = (__nv_bfloat16*)(shraw + FL_A_OFF);
    float* stats = (float*)(shraw + FL_ST_OFF);
    __nv_bfloat16* attnS = (__nv_bfloat16*)(shraw + FL_AT_OFF);

    const int tid  = threadIdx.x;
    const int lane = tid & 31;
    const int w    = tid >> 5;
    const int z    = blockIdx.y;
    const int m_blk = blockIdx.x * 64;

    const __nv_bfloat16* Ap = Q0 + (size_t)z * (P_ * D_) + (size_t)m_blk * D_;
    const __nv_bfloat16* Bp = K0 + (size_t)z * (P_ * D_);
    const __nv_bfloat16* Vp = V0 + (size_t)z * (P_ * D_);

    float acc[4][8][4];
    #pragma unroll
    for (int i = 0; i < 4; i++)
        #pragma unroll
        for (int j = 0; j < 8; j++)
            #pragma unroll
            for (int r = 0; r < 4; r++) acc[i][j][r] = 0.f;

    auto load_tile = [&](int k0, int buf) {
        __nv_bfloat16* Asb = As + buf * FL_ASTG;
        __nv_bfloat16* Bsb = Bs + buf * FL_BSTG;
        #pragma unroll
        for (int i = 0; i < 2; i++) {
            int idx = i * 256 + tid;
            int r = idx >> 3, c = (idx & 7) * 8;
            cpasync16(Asb + r * FL_SA + c, Ap + (size_t)r * D_ + k0 + c);
        }
        #pragma unroll
        for (int i = 0; i < 16; i++) {
            int idx = i * 256 + tid;
            int r = idx >> 3, c = (idx & 7) * 8;
            cpasync16(Bsb + r * FL_SA + c, Bp + (size_t)r * D_ + k0 + c);
        }
        asm volatile("cp.async.commit_group;\n");
    };
    auto load_v = [&](int k0, int buf) {
        __nv_bfloat16* Vsb = (__nv_bfloat16*)(shraw + FL_V_OFF) + buf * FL_VSTG;
        #pragma unroll
        for (int i = 0; i < 8; i++) {
            int idx = i * 256 + tid;
            int r = idx >> 3, c = (idx & 7) * 8;
            cpasync16(Vsb + r * FL_SA + c, Vp + (size_t)r * P_ + k0 + c);
        }
        asm volatile("cp.async.commit_group;\n");
    };

    constexpr int NT = D_ / 64;
    load_tile(0, 0);

    const int g  = lane >> 3;
    const int rw = lane & 7;
    const uint32_t aBase = smem_u32(As)
        + ((uint32_t)(((g & 1) * 8 + rw) * FL_SA + (g >> 1) * 8) << 1);
    const uint32_t bBase = smem_u32(Bs)
        + ((uint32_t)((w * 64 + (g >> 1) * 8 + rw) * FL_SA + (g & 1) * 8) << 1);

    #pragma unroll 1
    for (int t = 0; t < NT; t++) {
        if (t + 1 < NT) {
            load_tile((t + 1) * 64, (t + 1) & 1);
            asm volatile("cp.async.wait_group 1;\n");
        } else {
            asm volatile("cp.async.wait_group 0;\n");
        }
        __syncthreads();

        const uint32_t sA = aBase + ((uint32_t)((t & 1) * FL_ASTG) << 1);
        const uint32_t sB = bBase + ((uint32_t)((t & 1) * FL_BSTG) << 1);

        #pragma unroll
        for (int ks = 0; ks < 64; ks += 16) {
            uint32_t afr[4][4];
            #pragma unroll
            for (int i = 0; i < 4; i++)
                ldsm4(afr[i][0], afr[i][1], afr[i][2], afr[i][3],
                      sA + (uint32_t)((i * 16 * FL_SA + ks) << 1));
            uint32_t bfr[8][2];
            #pragma unroll
            for (int j2 = 0; j2 < 4; j2++)
                ldsm4(bfr[2 * j2][0], bfr[2 * j2][1],
                      bfr[2 * j2 + 1][0], bfr[2 * j2 + 1][1],
                      sB + (uint32_t)((j2 * 16 * FL_SA + ks) << 1));
            #pragma unroll
            for (int i = 0; i < 4; i++)
                #pragma unroll
                for (int j = 0; j < 8; j++)
                    mma_bf16(acc[i][j], afr[i], bfr[j]);
        }
        __syncthreads();
    }

    load_v(0, 0);

    // ----- softmax (fp32) -----
    const int q4 = lane >> 2;
    float lm[4][2];
    #pragma unroll
    for (int i = 0; i < 4; i++)
        #pragma unroll
        for (int h = 0; h < 2; h++) {
            float m = -1e30f;
            #pragma unroll
            for (int j = 0; j < 8; j++)
                m = fmaxf(m, fmaxf(acc[i][j][2 * h], acc[i][j][2 * h + 1]));
            m = fmaxf(m, __shfl_xor_sync(0xffffffffu, m, 1));
            m = fmaxf(m, __shfl_xor_sync(0xffffffffu, m, 2));
            lm[i][h] = m;
        }
    if ((lane & 3) == 0) {
        #pragma unroll
        for (int i = 0; i < 4; i++)
            #pragma unroll
            for (int h = 0; h < 2; h++)
                stats[(i * 16 + h * 8 + q4) * 8 + w] = lm[i][h];
    }
    __syncthreads();
    float gm[4][2];
    #pragma unroll
    for (int i = 0; i < 4; i++)
        #pragma unroll
        for (int h = 0; h < 2; h++) {
            const float* sp = stats + (i * 16 + h * 8 + q4) * 8;
            float m = sp[0];
            #pragma unroll
            for (int ww = 1; ww < 8; ww++) m = fmaxf(m, sp[ww]);
            gm[i][h] = m;
        }
    __syncthreads();
    float ls[4][2];
    #pragma unroll
    for (int i = 0; i < 4; i++)
        #pragma unroll
        for (int h = 0; h < 2; h++) {
            float s = 0.f;
            #pragma unroll
            for (int j = 0; j < 8; j++) {
                float e0 = __expf(acc[i][j][2 * h]     - gm[i][h]);
                float e1 = __expf(acc[i][j][2 * h + 1] - gm[i][h]);
                acc[i][j][2 * h]     = e0;
                acc[i][j][2 * h + 1] = e1;
                s += e0 + e1;
            }
            s += __shfl_xor_sync(0xffffffffu, s, 1);
            s += __shfl_xor_sync(0xffffffffu, s, 2);
            ls[i][h] = s;
        }
    if ((lane & 3) == 0) {
        #pragma unroll
        for (int i = 0; i < 4; i++)
            #pragma unroll
            for (int h = 0; h < 2; h++)
                stats[(i * 16 + h * 8 + q4) * 8 + w] = ls[i][h];
    }
    __syncthreads();
    float inv[4][2];
    #pragma unroll
    for (int i = 0; i < 4; i++)
        #pragma unroll
        for (int h = 0; h < 2; h++) {
            const float* sp = stats + (i * 16 + h * 8 + q4) * 8;
            float s = sp[0];
            #pragma unroll
            for (int ww = 1; ww < 8; ww++) s += sp[ww];
            inv[i][h] = 1.0f / s;
        }

    #pragma unroll
    for (int j = 0; j < 8; j++) {
        int cidx = w * 64 + j * 8 + 2 * (lane & 3);
        #pragma unroll
        for (int i = 0; i < 4; i++) {
            int r0 = i * 16 + q4;
            *(uint32_t*)(attnS + (size_t)r0 * FL_SA2 + cidx) =
                packbf(acc[i][j][0] * inv[i][0], acc[i][j][1] * inv[i][0]);
            *(uint32_t*)(attnS + (size_t)(r0 + 8) * FL_SA2 + cidx) =
                packbf(acc[i][j][2] * inv[i][1], acc[i][j][3] * inv[i][1]);
        }
    }

    // ----- phase 2 -----
    float acc2[4][4][4];
    #pragma unroll
    for (int i = 0; i < 4; i++)
        #pragma unroll
        for (int j = 0; j < 4; j++)
            #pragma unroll
            for (int r = 0; r < 4; r++) acc2[i][j][r] = 0.f;

    const uint32_t aBase2 = smem_u32(attnS)
        + ((uint32_t)(((g & 1) * 8 + rw) * FL_SA2 + (g >> 1) * 8) << 1);
    const uint32_t bBase2 = smem_u32(shraw + FL_V_OFF)
        + ((uint32_t)((w * 32 + (g >> 1) * 8 + rw) * FL_SA + (g & 1) * 8) << 1);

    #pragma unroll 1
    for (int t2 = 0; t2 < 8; t2++) {
        if (t2 + 1 < 8) {
            load_v((t2 + 1) * 64, (t2 + 1) & 1);
            asm volatile("cp.async.wait_group 1;\n");
        } else {
            asm volatile("cp.async.wait_group 0;\n");
        }
        __syncthreads();

        const uint32_t sB = bBase2 + ((uint32_t)((t2 & 1) * FL_VSTG) << 1);

        #pragma unroll
        for (int ks = 0; ks < 64; ks += 16) {
            uint32_t afr[4][4];
            #pragma unroll
            for (int i = 0; i < 4; i++)
                ldsm4(afr[i][0], afr[i][1], afr[i][2], afr[i][3],
                      aBase2 + (uint32_t)((i * 16 * FL_SA2 + t2 * 64 + ks) << 1));
            uint32_t bfr[4][2];
            #pragma unroll
            for (int j2 = 0; j2 < 2; j2++)
                ldsm4(bfr[2 * j2][0], bfr[2 * j2][1],
                      bfr[2 * j2 + 1][0], bfr[2 * j2 + 1][1],
                      sB + (uint32_t)((j2 * 16 * FL_SA + ks) << 1));
            #pragma unroll
            for (int i = 0; i < 4; i++)
                #pragma unroll
                for (int j = 0; j < 4; j++)
                    mma_bf16(acc2[i][j], afr[i], bfr[j]);
        }
        __syncthreads();
    }

    float* Op = O0 + (size_t)z * (P_ * D_) + (size_t)m_blk * D_;
    #pragma unroll
    for (int j = 0; j < 4; j++) {
        int cidx = w * 32 + j * 8 + 2 * (lane & 3);
        #pragma unroll
        for (int i = 0; i < 4; i++) {
            int r0 = i * 16 + q4;
            *(float2*)(Op + (size_t)r0 * D_ + cidx) =
                make_float2(acc2[i][j][0], acc2[i][j][1]);
            *(float2*)(Op + (size_t)(r0 + 8) * D_ + cidx) =
                make_float2(acc2[i][j][2], acc2[i][j][3]);
        }
    }
}

// ---------------------------------------------------------------------------
// launch
// ---------------------------------------------------------------------------
extern "C" void kernel_launch(void* const* d_in, const int* in_sizes, int n_in,
                              void* d_out, int out_size)
{
    const float* query = (const float*)d_in[0];
    const float* aw    = (const float*)d_in[1];
    const float* wq    = (const float*)d_in[2];
    const float* wk    = (const float*)d_in[3];
    const float* wv    = (const float*)d_in[4];
    const float* bq    = (const float*)d_in[5];
    const float* bk    = (const float*)d_in[6];
    const float* bv    = (const float*)d_in[7];
    float* out = (float*)d_out;

    __nv_bfloat16 *gctx, *gqr, *gq, *gk, *gvT, *gwqT, *gwkT, *gwvT;
    cudaGetSymbolAddress((void**)&gctx, g_context);
    cudaGetSymbolAddress((void**)&gqr, g_qr);
    cudaGetSymbolAddress((void**)&gq, g_q);
    cudaGetSymbolAddress((void**)&gk, g_k);
    cudaGetSymbolAddress((void**)&gvT, g_vT);
    cudaGetSymbolAddress((void**)&gwqT, g_wqT);
    cudaGetSymbolAddress((void**)&gwkT, g_wkT);
    cudaGetSymbolAddress((void**)&gwvT, g_wvT);

    constexpr int SMEM_BYTES = 2 * 2 * 128 * 72 * 2;   // 73728
    cudaFuncSetAttribute(proj_gemm, cudaFuncAttributeMaxDynamicSharedMemorySize, SMEM_BYTES);
    cudaFuncSetAttribute(fused_attn_kernel, cudaFuncAttributeMaxDynamicSharedMemorySize, FL_SMEM);

    const float qscale = 1.0f / 16.0f;   // D^-0.5
    const int BC = B_ * C_;

    // 0) transpose weights to bf16 [c][e][d]
    transpose_w_kernel<<<dim3(8, 8, 3 * C_), dim3(32, 8)>>>(wq, wk, wv);

    // 1) context + query (bf16)
    context_kernel<<<(B_ * P_ * D_ / 2 + 255) / 256, 256>>>(query, aw);

    // 2) all three projections in one launch
    proj_gemm<<<dim3(8, 3 * BC), 128, SMEM_BYTES>>>(
        gqr, gctx, gwqT, gwkT, gwvT, bq, bk, bv, gq, gk, gvT, qscale);

    // 3) fully fused attention -> out (fp32)
    fused_attn_kernel<<<dim3(8, BC), 256, FL_SMEM>>>(gq, gk, gvT, out);
}